// round 6
// baseline (speedup 1.0000x reference)
#include <cuda_runtime.h>
#include <cuda_bf16.h>
#include <cstdint>

#define TN   32768
#define D    128
#define BG   64
#define NG   512
#define ET   524288
#define NH   4
#define CAP  96

typedef unsigned long long u64;

// ---------------- scratch ----------------
__device__ float g_h  [TN * D];
__device__ float g_h2 [TN * D];
__device__ float g_q  [TN * D];
__device__ float g_kv [TN * 256];
__device__ float g_ao [TN * D];
__device__ float g_wt [640 * 128];   // wt0@0 (gcn), wt1@16384 (q), wt2@32768 (kv), wt3@65536 (out)
__device__ float g_deg[TN];
__device__ int   g_cnt[TN];
__device__ u64   g_bkt[TN * CAP];

// ---------------- f32x2 helpers ----------------
#define FMA2(d,a,b) asm("fma.rn.f32x2 %0, %1, %2, %0;" : "+l"(d) : "l"(a), "l"(b))
#define MUL2(d,a)   asm("mul.rn.f32x2 %0, %0, %1;"     : "+l"(d) : "l"(a))

__device__ __forceinline__ u64 pk2(float lo, float hi) {
    u64 r;
    asm("mov.b64 %0, {%1, %2};" : "=l"(r)
        : "r"(__float_as_uint(lo)), "r"(__float_as_uint(hi)));
    return r;
}
__device__ __forceinline__ float hadd2(u64 v) {
    unsigned int lo, hi;
    asm("mov.b64 {%0, %1}, %2;" : "=r"(lo), "=r"(hi) : "l"(v));
    return __uint_as_float(lo) + __uint_as_float(hi);
}

// ---------------- K0: fused init + weight transposes ----------------
// blocks [0,128): init deg/cnt; blocks [128,256): transpose 4 weight matrices
__global__ void init_wtrans_kernel(const float* __restrict__ Wg,
                                   const float* __restrict__ Wq,
                                   const float* __restrict__ Wkv,
                                   const float* __restrict__ Wo) {
    __shared__ float t[32][33];
    int bid = blockIdx.x;
    if (bid < 128) {
        int i = bid * 256 + threadIdx.y * 32 + threadIdx.x;
        g_deg[i] = 1.0f;
        g_cnt[i] = 0;
        return;
    }
    int w = bid - 128;            // 0..127
    int z  = w >> 5;              // matrix id
    int by = (w >> 3) & 3;        // k tile
    int bx = w & 7;               // col tile
    const float* W; float* WT; int ncols;
    if (z == 0)      { W = Wg;  WT = g_wt;          ncols = 128; }
    else if (z == 1) { W = Wq;  WT = g_wt + 16384;  ncols = 128; }
    else if (z == 2) { W = Wkv; WT = g_wt + 32768;  ncols = 256; }
    else             { W = Wo;  WT = g_wt + 65536;  ncols = 128; }
    if (bx * 32 >= ncols) return;
    int c = bx * 32 + threadIdx.x;
    int k = by * 32 + threadIdx.y;
#pragma unroll
    for (int i = 0; i < 32; i += 8)
        t[threadIdx.y + i][threadIdx.x] = W[(k + i) * ncols + c];
    __syncthreads();
    int c2 = bx * 32 + threadIdx.y;
    int k2 = by * 32 + threadIdx.x;
#pragma unroll
    for (int i = 0; i < 32; i += 8)
        WT[(c2 + i) * 128 + k2] = t[threadIdx.x][threadIdx.y + i];
}

// ---------------- K1: out-degree atomics + bucket scatter by dst ----------------
__global__ void scatter_kernel(const int* __restrict__ ei) {
    int e = blockIdx.x * blockDim.x + threadIdx.x;
    if (e < ET) {
        int r = ei[e];
        int c = ei[ET + e];
        atomicAdd(&g_deg[r], 1.0f);
        int pos = atomicAdd(&g_cnt[c], 1);
        if (pos < CAP)
            g_bkt[(long long)c * CAP + pos] = (u64)(unsigned)e | ((u64)(unsigned)r << 32);
    }
}

// ---------------- GEMM body (f32x2, 128x64 tile, identical math to R4) ----------------
__device__ __forceinline__ void gemm_body(const float* __restrict__ A,
                                          const float* __restrict__ WTpart,
                                          const float* __restrict__ biasPart,
                                          float* __restrict__ out,
                                          int out_ld4, int out_col4,
                                          float* sm) {
    float* As  = sm;             // 128*128
    float* WsT = sm + 128 * 128; // 64*130
    int tid = threadIdx.x;
    long long m0 = (long long)blockIdx.x * 128;

    const float4* A4 = (const float4*)(A + m0 * 128);
    float4* As4 = (float4*)As;
#pragma unroll
    for (int i = 0; i < 16; i++) As4[tid + i * 256] = A4[tid + i * 256];

    const float4* WT4 = (const float4*)WTpart;
#pragma unroll
    for (int i = 0; i < 8; i++) {
        int idx = tid + i * 256;
        int c  = idx >> 5;
        int k4 = idx & 31;
        float4 w = WT4[idx];
        u64* dst = (u64*)(WsT + c * 130 + k4 * 4);
        dst[0] = ((const u64*)&w)[0];
        dst[1] = ((const u64*)&w)[1];
    }
    __syncthreads();

    int cg = tid & 15;
    int rg = tid >> 4;
    int c0 = cg * 4, r0 = rg * 8;

    u64 acc[8][4];
#pragma unroll
    for (int i = 0; i < 8; i++)
#pragma unroll
        for (int j = 0; j < 4; j++) acc[i][j] = 0ull;

    const u64* Au = (const u64*)As;
    const u64* Wu = (const u64*)WsT;

#pragma unroll 4
    for (int kk = 0; kk < 64; kk++) {
        u64 w2[4];
#pragma unroll
        for (int ci = 0; ci < 4; ci++) w2[ci] = Wu[(c0 + ci) * 65 + kk];
#pragma unroll
        for (int ri = 0; ri < 8; ri++) {
            u64 a2 = Au[(r0 + ri) * 64 + kk];
#pragma unroll
            for (int ci = 0; ci < 4; ci++) FMA2(acc[ri][ci], a2, w2[ci]);
        }
    }

    float4 bv = make_float4(0.f, 0.f, 0.f, 0.f);
    if (biasPart) bv = ((const float4*)biasPart)[cg];
    float4* O4 = (float4*)out;
#pragma unroll
    for (int ri = 0; ri < 8; ri++) {
        float4 o;
        o.x = hadd2(acc[ri][0]) + bv.x;
        o.y = hadd2(acc[ri][1]) + bv.y;
        o.z = hadd2(acc[ri][2]) + bv.z;
        o.w = hadd2(acc[ri][3]) + bv.w;
        O4[(m0 + r0 + ri) * out_ld4 + out_col4 + cg] = o;
    }
}

// standard GEMM: (TN x 128) @ (128 x ncols)
__global__ void __launch_bounds__(256, 2)
gemm_kernel(const float* __restrict__ A, const float* __restrict__ WT,
            int ncols, const float* __restrict__ bias, float* __restrict__ out) {
    extern __shared__ float sm[];
    int cb = blockIdx.y * 64;
    gemm_body(A, WT + cb * 128, bias ? bias + cb : nullptr,
              out, ncols >> 2, cb >> 2, sm);
}

// fused q + kv projections: grid.y in [0,6)
__global__ void __launch_bounds__(256, 2)
qkv_gemm_kernel(const float* __restrict__ A) {
    extern __shared__ float sm[];
    int y = blockIdx.y;
    if (y < 2) {
        int cb = y * 64;
        gemm_body(A, g_wt + 16384 + cb * 128, nullptr, g_q, 32, cb >> 2, sm);
    } else {
        int cb = (y - 2) * 64;
        gemm_body(A, g_wt + 32768 + cb * 128, nullptr, g_kv, 64, cb >> 2, sm);
    }
}

// ---------------- K3: gather + finalize (dinv inlined) ----------------
__global__ void gather_kernel(const float* __restrict__ ee,
                              const float* __restrict__ root) {
    int gw = (blockIdx.x * blockDim.x + threadIdx.x) >> 5;
    int lane = threadIdx.x & 31;
    if (gw >= TN) return;
    int n = gw;
    float degn = g_deg[n];
    float dc = rsqrtf(degn);
    int cnt = g_cnt[n]; if (cnt > CAP) cnt = CAP;
    const float4* h4 = (const float4*)g_h;
    const float4* e4 = (const float4*)ee;
    const u64* bkt = g_bkt + (long long)n * CAP;
    float4 acc = make_float4(0.f, 0.f, 0.f, 0.f);
    for (int p = 0; p < cnt; ++p) {
        u64 pr = bkt[p];
        int eid = (int)(unsigned)pr;
        int r   = (int)(unsigned)(pr >> 32);
        float norm = dc * rsqrtf(g_deg[r]);
        float4 hv = h4[r * 32 + lane];
        float4 ev = e4[(long long)eid * 32 + lane];
        acc.x += norm * fmaxf(hv.x + ev.x, 0.f);
        acc.y += norm * fmaxf(hv.y + ev.y, 0.f);
        acc.z += norm * fmaxf(hv.z + ev.z, 0.f);
        acc.w += norm * fmaxf(hv.w + ev.w, 0.f);
    }
    float4 hs = h4[n * 32 + lane];
    float4 rt = ((const float4*)root)[lane];
    float inv = 1.0f / degn;
    acc.x += fmaxf(hs.x + rt.x, 0.f) * inv;
    acc.y += fmaxf(hs.y + rt.y, 0.f) * inv;
    acc.z += fmaxf(hs.z + rt.z, 0.f) * inv;
    acc.w += fmaxf(hs.w + rt.w, 0.f) * inv;
    ((float4*)g_h2)[n * 32 + lane] = acc;
}

// ---------------- attention (frozen R2/R4 version) ----------------
__global__ void __launch_bounds__(256) attn_kernel() {
    extern __shared__ float sm[];
    float4* Ks4 = (float4*)sm;          // 512*8 float4 = 64KB
    float4* Vs4 = Ks4 + 512 * 8;        // 64KB
    int tid = threadIdx.x;
    int b = blockIdx.x >> 2;
    int h = blockIdx.x & 3;
    int nbase = b * NG;

    const float4* KV4 = (const float4*)g_kv;
    for (int idx = tid; idx < NG * 8; idx += 256) {
        int j  = idx >> 3;
        int d4 = idx & 7;
        Ks4[idx] = KV4[(nbase + j) * 64 + h * 8 + d4];
        Vs4[idx] = KV4[(nbase + j) * 64 + 32 + h * 8 + d4];
    }
    __syncthreads();

    const float scale = 0.17677669529663687f;
    u64 q0[16], q1[16];
    const float4* Q4 = (const float4*)g_q;
#pragma unroll
    for (int d4 = 0; d4 < 8; d4++) {
        float4 a = Q4[(nbase + tid) * 32 + h * 8 + d4];
        q0[2 * d4]     = pk2(a.x * scale, a.y * scale);
        q0[2 * d4 + 1] = pk2(a.z * scale, a.w * scale);
        float4 c = Q4[(nbase + tid + 256) * 32 + h * 8 + d4];
        q1[2 * d4]     = pk2(c.x * scale, c.y * scale);
        q1[2 * d4 + 1] = pk2(c.z * scale, c.w * scale);
    }

    u64 o0[16], o1[16];
#pragma unroll
    for (int d = 0; d < 16; d++) { o0[d] = 0ull; o1[d] = 0ull; }
    float m0 = -1e30f, l0 = 0.f, m1 = -1e30f, l1 = 0.f;

    for (int jt = 0; jt < NG; jt += 8) {
        float s0[8], s1[8];
#pragma unroll
        for (int jj = 0; jj < 8; jj++) {
            const ulonglong2* kp = (const ulonglong2*)(Ks4 + (jt + jj) * 8);
            u64 a0 = 0ull, b0 = 0ull, a1 = 0ull, b1 = 0ull;
#pragma unroll
            for (int d = 0; d < 8; d++) {
                ulonglong2 kk = kp[d];
                FMA2(a0, q0[2 * d], kk.x);
                FMA2(b0, q0[2 * d + 1], kk.y);
                FMA2(a1, q1[2 * d], kk.x);
                FMA2(b1, q1[2 * d + 1], kk.y);
            }
            s0[jj] = hadd2(a0) + hadd2(b0);
            s1[jj] = hadd2(a1) + hadd2(b1);
        }
        float tm0 = s0[0], tm1 = s1[0];
#pragma unroll
        for (int jj = 1; jj < 8; jj++) { tm0 = fmaxf(tm0, s0[jj]); tm1 = fmaxf(tm1, s1[jj]); }
        float nm0 = fmaxf(m0, tm0), nm1 = fmaxf(m1, tm1);
        float al0 = __expf(m0 - nm0), al1 = __expf(m1 - nm1);
        m0 = nm0; m1 = nm1;
        l0 *= al0; l1 *= al1;
        u64 al0p = pk2(al0, al0), al1p = pk2(al1, al1);
#pragma unroll
        for (int d = 0; d < 16; d++) { MUL2(o0[d], al0p); MUL2(o1[d], al1p); }
#pragma unroll
        for (int jj = 0; jj < 8; jj++) {
            float p0 = __expf(s0[jj] - m0); l0 += p0;
            float p1 = __expf(s1[jj] - m1); l1 += p1;
            u64 p0p = pk2(p0, p0), p1p = pk2(p1, p1);
            const ulonglong2* vp = (const ulonglong2*)(Vs4 + (jt + jj) * 8);
#pragma unroll
            for (int d = 0; d < 8; d++) {
                ulonglong2 vv = vp[d];
                FMA2(o0[2 * d],     p0p, vv.x);
                FMA2(o0[2 * d + 1], p0p, vv.y);
                FMA2(o1[2 * d],     p1p, vv.x);
                FMA2(o1[2 * d + 1], p1p, vv.y);
            }
        }
    }

    float inv0 = 1.0f / l0, inv1 = 1.0f / l1;
    u64 i0p = pk2(inv0, inv0), i1p = pk2(inv1, inv1);
    ulonglong2* O = (ulonglong2*)g_ao;
#pragma unroll
    for (int d = 0; d < 8; d++) {
        MUL2(o0[2 * d], i0p); MUL2(o0[2 * d + 1], i0p);
        MUL2(o1[2 * d], i1p); MUL2(o1[2 * d + 1], i1p);
        O[(nbase + tid) * 32 + h * 8 + d]       = make_ulonglong2(o0[2 * d], o0[2 * d + 1]);
        O[(nbase + tid + 256) * 32 + h * 8 + d] = make_ulonglong2(o1[2 * d], o1[2 * d + 1]);
    }
}

// ---------------- launch ----------------
extern "C" void kernel_launch(void* const* d_in, const int* in_sizes, int n_in,
                              void* d_out, int out_size) {
    const float* x    = (const float*)d_in[0];
    const int*   ei   = (const int*)d_in[1];
    const float* ee   = (const float*)d_in[2];
    const float* Wg   = (const float*)d_in[4];
    const float* bg   = (const float*)d_in[5];
    const float* root = (const float*)d_in[6];
    const float* Wq   = (const float*)d_in[7];
    const float* Wkv  = (const float*)d_in[8];
    const float* Wo   = (const float*)d_in[9];
    const float* bo   = (const float*)d_in[10];
    float* outp = (float*)d_out;

    float *p_h, *p_h2, *p_ao, *p_wt;
    cudaGetSymbolAddress((void**)&p_h,  g_h);
    cudaGetSymbolAddress((void**)&p_h2, g_h2);
    cudaGetSymbolAddress((void**)&p_ao, g_ao);
    cudaGetSymbolAddress((void**)&p_wt, g_wt);

    const int GEMM_SMEM = (128 * 128 + 64 * 130) * 4;
    const int ATTN_SMEM = 128 * 1024;
    cudaFuncSetAttribute(gemm_kernel,     cudaFuncAttributeMaxDynamicSharedMemorySize, GEMM_SMEM);
    cudaFuncSetAttribute(qkv_gemm_kernel, cudaFuncAttributeMaxDynamicSharedMemorySize, GEMM_SMEM);
    cudaFuncSetAttribute(attn_kernel,     cudaFuncAttributeMaxDynamicSharedMemorySize, ATTN_SMEM);

    // 0: init + all weight transposes (fused)
    init_wtrans_kernel<<<256, dim3(32, 8)>>>(Wg, Wq, Wkv, Wo);
    // 1: degree atomics + bucket scatter
    scatter_kernel<<<ET / 256, 256>>>(ei);
    // 2: h = x @ W_gcn + b_gcn
    gemm_kernel<<<dim3(TN / 128, 2), 256, GEMM_SMEM>>>(x, p_wt, 128, bg, p_h);
    // 3: gather -> h2  (PROFILED SLOT)
    gather_kernel<<<TN / 8, 256>>>(ee, root);
    // 4: fused q + kv projections
    qkv_gemm_kernel<<<dim3(TN / 128, 6), 256, GEMM_SMEM>>>(p_h2);
    // 5: attention
    attn_kernel<<<BG * NH, 256, ATTN_SMEM>>>();
    // 6: out = ao @ Wout + b_out
    gemm_kernel<<<dim3(TN / 128, 2), 256, GEMM_SMEM>>>(p_ao, p_wt + 65536, 128, bo, outp);
}

// round 7
// speedup vs baseline: 1.0262x; 1.0262x over previous
#include <cuda_runtime.h>
#include <cuda_bf16.h>
#include <cstdint>

#define TN   32768
#define D    128
#define BG   64
#define NG   512
#define ET   524288
#define NH   4
#define CAP  96

typedef unsigned long long u64;

// ---------------- scratch ----------------
__device__ float g_h  [TN * D];
__device__ float g_h2 [TN * D];
__device__ float g_q  [TN * D];
__device__ float g_kv [TN * 256];
__device__ float g_ao [TN * D];
__device__ float g_wt [640 * 128];   // wt0@0 (gcn), wt1@16384 (q), wt2@32768 (kv), wt3@65536 (out)
__device__ float g_deg[TN];
__device__ int   g_cnt[TN];
__device__ u64   g_bkt[TN * CAP];

// ---------------- f32x2 helpers ----------------
#define FMA2(d,a,b) asm("fma.rn.f32x2 %0, %1, %2, %0;" : "+l"(d) : "l"(a), "l"(b))
#define MUL2(d,a)   asm("mul.rn.f32x2 %0, %0, %1;"     : "+l"(d) : "l"(a))

__device__ __forceinline__ u64 pk2(float lo, float hi) {
    u64 r;
    asm("mov.b64 %0, {%1, %2};" : "=l"(r)
        : "r"(__float_as_uint(lo)), "r"(__float_as_uint(hi)));
    return r;
}
__device__ __forceinline__ float hadd2(u64 v) {
    unsigned int lo, hi;
    asm("mov.b64 {%0, %1}, %2;" : "=r"(lo), "=r"(hi) : "l"(v));
    return __uint_as_float(lo) + __uint_as_float(hi);
}

// ---------------- K0: fused init + weight transposes ----------------
__global__ void init_wtrans_kernel(const float* __restrict__ Wg,
                                   const float* __restrict__ Wq,
                                   const float* __restrict__ Wkv,
                                   const float* __restrict__ Wo) {
    __shared__ float t[32][33];
    int bid = blockIdx.x;
    if (bid < 128) {
        int i = bid * 256 + threadIdx.y * 32 + threadIdx.x;
        g_deg[i] = 1.0f;
        g_cnt[i] = 0;
        return;
    }
    int w = bid - 128;            // 0..127
    int z  = w >> 5;
    int by = (w >> 3) & 3;
    int bx = w & 7;
    const float* W; float* WT; int ncols;
    if (z == 0)      { W = Wg;  WT = g_wt;          ncols = 128; }
    else if (z == 1) { W = Wq;  WT = g_wt + 16384;  ncols = 128; }
    else if (z == 2) { W = Wkv; WT = g_wt + 32768;  ncols = 256; }
    else             { W = Wo;  WT = g_wt + 65536;  ncols = 128; }
    if (bx * 32 >= ncols) return;
    int c = bx * 32 + threadIdx.x;
    int k = by * 32 + threadIdx.y;
#pragma unroll
    for (int i = 0; i < 32; i += 8)
        t[threadIdx.y + i][threadIdx.x] = W[(k + i) * ncols + c];
    __syncthreads();
    int c2 = bx * 32 + threadIdx.y;
    int k2 = by * 32 + threadIdx.x;
#pragma unroll
    for (int i = 0; i < 32; i += 8)
        WT[(c2 + i) * 128 + k2] = t[threadIdx.x][threadIdx.y + i];
}

// ---------------- GEMM body (f32x2, 128x64 tile) ----------------
__device__ __forceinline__ void gemm_body(const float* __restrict__ A,
                                          long long m0,
                                          const float* __restrict__ WTpart,
                                          const float* __restrict__ biasPart,
                                          float* __restrict__ out,
                                          int out_ld4, int out_col4,
                                          float* sm) {
    float* As  = sm;             // 128*128
    float* WsT = sm + 128 * 128; // 64*130
    int tid = threadIdx.x;

    const float4* A4 = (const float4*)(A + m0 * 128);
    float4* As4 = (float4*)As;
#pragma unroll
    for (int i = 0; i < 16; i++) As4[tid + i * 256] = A4[tid + i * 256];

    const float4* WT4 = (const float4*)WTpart;
#pragma unroll
    for (int i = 0; i < 8; i++) {
        int idx = tid + i * 256;
        int c  = idx >> 5;
        int k4 = idx & 31;
        float4 w = WT4[idx];
        u64* dst = (u64*)(WsT + c * 130 + k4 * 4);
        dst[0] = ((const u64*)&w)[0];
        dst[1] = ((const u64*)&w)[1];
    }
    __syncthreads();

    int cg = tid & 15;
    int rg = tid >> 4;
    int c0 = cg * 4, r0 = rg * 8;

    u64 acc[8][4];
#pragma unroll
    for (int i = 0; i < 8; i++)
#pragma unroll
        for (int j = 0; j < 4; j++) acc[i][j] = 0ull;

    const u64* Au = (const u64*)As;
    const u64* Wu = (const u64*)WsT;

#pragma unroll 4
    for (int kk = 0; kk < 64; kk++) {
        u64 w2[4];
#pragma unroll
        for (int ci = 0; ci < 4; ci++) w2[ci] = Wu[(c0 + ci) * 65 + kk];
#pragma unroll
        for (int ri = 0; ri < 8; ri++) {
            u64 a2 = Au[(r0 + ri) * 64 + kk];
#pragma unroll
            for (int ci = 0; ci < 4; ci++) FMA2(acc[ri][ci], a2, w2[ci]);
        }
    }

    float4 bv = make_float4(0.f, 0.f, 0.f, 0.f);
    if (biasPart) bv = ((const float4*)biasPart)[cg];
    float4* O4 = (float4*)out;
#pragma unroll
    for (int ri = 0; ri < 8; ri++) {
        float4 o;
        o.x = hadd2(acc[ri][0]) + bv.x;
        o.y = hadd2(acc[ri][1]) + bv.y;
        o.z = hadd2(acc[ri][2]) + bv.z;
        o.w = hadd2(acc[ri][3]) + bv.w;
        O4[(m0 + r0 + ri) * out_ld4 + out_col4 + cg] = o;
    }
}

// ---------------- K1: fused scatter + GCN GEMM (interleaved 1:4) ----------------
// 2560 blocks: bid%5==0 -> gemm tile (512), else -> scatter chunk (2048)
__global__ void __launch_bounds__(256, 2)
scatter_gcn_kernel(const int* __restrict__ ei, const float* __restrict__ x,
                   const float* __restrict__ bg) {
    extern __shared__ float sm[];
    int bid = blockIdx.x;
    if (bid % 5 == 0) {
        int gid = bid / 5;               // 0..511
        int bx = gid & 255, by = gid >> 8;
        int cb = by * 64;
        gemm_body(x, (long long)bx * 128, g_wt + cb * 128, bg + cb,
                  g_h, 32, cb >> 2, sm);
    } else {
        int sid = bid - (bid / 5 + 1);   // 0..2047
        int e = sid * 256 + threadIdx.x; // < ET always
        int r = ei[e];
        int c = ei[ET + e];
        atomicAdd(&g_deg[r], 1.0f);
        int pos = atomicAdd(&g_cnt[c], 1);
        if (pos < CAP)
            g_bkt[(long long)c * CAP + pos] = (u64)(unsigned)e | ((u64)(unsigned)r << 32);
    }
}

// standard GEMM: (TN x 128) @ (128 x ncols)
__global__ void __launch_bounds__(256, 2)
gemm_kernel(const float* __restrict__ A, const float* __restrict__ WT,
            int ncols, const float* __restrict__ bias, float* __restrict__ out) {
    extern __shared__ float sm[];
    int cb = blockIdx.y * 64;
    gemm_body(A, (long long)blockIdx.x * 128, WT + cb * 128,
              bias ? bias + cb : nullptr, out, ncols >> 2, cb >> 2, sm);
}

// fused q + kv projections: grid.y in [0,6)
__global__ void __launch_bounds__(256, 2)
qkv_gemm_kernel(const float* __restrict__ A) {
    extern __shared__ float sm[];
    int y = blockIdx.y;
    if (y < 2) {
        int cb = y * 64;
        gemm_body(A, (long long)blockIdx.x * 128, g_wt + 16384 + cb * 128,
                  nullptr, g_q, 32, cb >> 2, sm);
    } else {
        int cb = (y - 2) * 64;
        gemm_body(A, (long long)blockIdx.x * 128, g_wt + 32768 + cb * 128,
                  nullptr, g_kv, 64, cb >> 2, sm);
    }
}

// ---------------- K2: gather (warp-batched, MLP-unrolled) ----------------
__global__ void gather_kernel(const float* __restrict__ ee,
                              const float* __restrict__ root) {
    int gw = (blockIdx.x * blockDim.x + threadIdx.x) >> 5;
    int lane = threadIdx.x & 31;
    if (gw >= TN) return;
    int n = gw;
    float degn = g_deg[n];
    float dc = rsqrtf(degn);
    int cnt = g_cnt[n]; if (cnt > CAP) cnt = CAP;
    const float4* h4 = (const float4*)g_h;
    const float4* e4 = (const float4*)ee;
    const u64* bkt = g_bkt + (long long)n * CAP;
    float4 acc = make_float4(0.f, 0.f, 0.f, 0.f);

    for (int base = 0; base < cnt; base += 32) {
        int m = min(32, cnt - base);
        // warp-cooperative entry load + per-entry norm precompute
        u64 pr = 0;
        if (lane < m) pr = bkt[base + lane];
        int r_l = (int)(unsigned)(pr >> 32);
        int e_l = (int)(unsigned)pr;
        float nm_l = 0.f;
        if (lane < m) nm_l = dc * rsqrtf(g_deg[r_l]);

        int p = 0;
        for (; p + 4 <= m; p += 4) {
            float4 hv[4], ev[4];
            float nm[4];
#pragma unroll
            for (int j = 0; j < 4; j++) {
                int r   = __shfl_sync(0xffffffffu, r_l, p + j);
                int eid = __shfl_sync(0xffffffffu, e_l, p + j);
                nm[j]   = __shfl_sync(0xffffffffu, nm_l, p + j);
                hv[j] = h4[r * 32 + lane];
                ev[j] = __ldcs(e4 + (long long)eid * 32 + lane);
            }
#pragma unroll
            for (int j = 0; j < 4; j++) {
                acc.x += nm[j] * fmaxf(hv[j].x + ev[j].x, 0.f);
                acc.y += nm[j] * fmaxf(hv[j].y + ev[j].y, 0.f);
                acc.z += nm[j] * fmaxf(hv[j].z + ev[j].z, 0.f);
                acc.w += nm[j] * fmaxf(hv[j].w + ev[j].w, 0.f);
            }
        }
        for (; p < m; p++) {
            int r   = __shfl_sync(0xffffffffu, r_l, p);
            int eid = __shfl_sync(0xffffffffu, e_l, p);
            float nm = __shfl_sync(0xffffffffu, nm_l, p);
            float4 hv = h4[r * 32 + lane];
            float4 ev = __ldcs(e4 + (long long)eid * 32 + lane);
            acc.x += nm * fmaxf(hv.x + ev.x, 0.f);
            acc.y += nm * fmaxf(hv.y + ev.y, 0.f);
            acc.z += nm * fmaxf(hv.z + ev.z, 0.f);
            acc.w += nm * fmaxf(hv.w + ev.w, 0.f);
        }
    }

    float4 hs = h4[n * 32 + lane];
    float4 rt = ((const float4*)root)[lane];
    float inv = 1.0f / degn;
    acc.x += fmaxf(hs.x + rt.x, 0.f) * inv;
    acc.y += fmaxf(hs.y + rt.y, 0.f) * inv;
    acc.z += fmaxf(hs.z + rt.z, 0.f) * inv;
    acc.w += fmaxf(hs.w + rt.w, 0.f) * inv;
    ((float4*)g_h2)[n * 32 + lane] = acc;
}

// ---------------- attention (frozen R2/R4 version) ----------------
__global__ void __launch_bounds__(256) attn_kernel() {
    extern __shared__ float sm[];
    float4* Ks4 = (float4*)sm;          // 512*8 float4 = 64KB
    float4* Vs4 = Ks4 + 512 * 8;        // 64KB
    int tid = threadIdx.x;
    int b = blockIdx.x >> 2;
    int h = blockIdx.x & 3;
    int nbase = b * NG;

    const float4* KV4 = (const float4*)g_kv;
    for (int idx = tid; idx < NG * 8; idx += 256) {
        int j  = idx >> 3;
        int d4 = idx & 7;
        Ks4[idx] = KV4[(nbase + j) * 64 + h * 8 + d4];
        Vs4[idx] = KV4[(nbase + j) * 64 + 32 + h * 8 + d4];
    }
    __syncthreads();

    const float scale = 0.17677669529663687f;
    u64 q0[16], q1[16];
    const float4* Q4 = (const float4*)g_q;
#pragma unroll
    for (int d4 = 0; d4 < 8; d4++) {
        float4 a = Q4[(nbase + tid) * 32 + h * 8 + d4];
        q0[2 * d4]     = pk2(a.x * scale, a.y * scale);
        q0[2 * d4 + 1] = pk2(a.z * scale, a.w * scale);
        float4 c = Q4[(nbase + tid + 256) * 32 + h * 8 + d4];
        q1[2 * d4]     = pk2(c.x * scale, c.y * scale);
        q1[2 * d4 + 1] = pk2(c.z * scale, c.w * scale);
    }

    u64 o0[16], o1[16];
#pragma unroll
    for (int d = 0; d < 16; d++) { o0[d] = 0ull; o1[d] = 0ull; }
    float m0 = -1e30f, l0 = 0.f, m1 = -1e30f, l1 = 0.f;

    for (int jt = 0; jt < NG; jt += 8) {
        float s0[8], s1[8];
#pragma unroll
        for (int jj = 0; jj < 8; jj++) {
            const ulonglong2* kp = (const ulonglong2*)(Ks4 + (jt + jj) * 8);
            u64 a0 = 0ull, b0 = 0ull, a1 = 0ull, b1 = 0ull;
#pragma unroll
            for (int d = 0; d < 8; d++) {
                ulonglong2 kk = kp[d];
                FMA2(a0, q0[2 * d], kk.x);
                FMA2(b0, q0[2 * d + 1], kk.y);
                FMA2(a1, q1[2 * d], kk.x);
                FMA2(b1, q1[2 * d + 1], kk.y);
            }
            s0[jj] = hadd2(a0) + hadd2(b0);
            s1[jj] = hadd2(a1) + hadd2(b1);
        }
        float tm0 = s0[0], tm1 = s1[0];
#pragma unroll
        for (int jj = 1; jj < 8; jj++) { tm0 = fmaxf(tm0, s0[jj]); tm1 = fmaxf(tm1, s1[jj]); }
        float nm0 = fmaxf(m0, tm0), nm1 = fmaxf(m1, tm1);
        float al0 = __expf(m0 - nm0), al1 = __expf(m1 - nm1);
        m0 = nm0; m1 = nm1;
        l0 *= al0; l1 *= al1;
        u64 al0p = pk2(al0, al0), al1p = pk2(al1, al1);
#pragma unroll
        for (int d = 0; d < 16; d++) { MUL2(o0[d], al0p); MUL2(o1[d], al1p); }
#pragma unroll
        for (int jj = 0; jj < 8; jj++) {
            float p0 = __expf(s0[jj] - m0); l0 += p0;
            float p1 = __expf(s1[jj] - m1); l1 += p1;
            u64 p0p = pk2(p0, p0), p1p = pk2(p1, p1);
            const ulonglong2* vp = (const ulonglong2*)(Vs4 + (jt + jj) * 8);
#pragma unroll
            for (int d = 0; d < 8; d++) {
                ulonglong2 vv = vp[d];
                FMA2(o0[2 * d],     p0p, vv.x);
                FMA2(o0[2 * d + 1], p0p, vv.y);
                FMA2(o1[2 * d],     p1p, vv.x);
                FMA2(o1[2 * d + 1], p1p, vv.y);
            }
        }
    }

    float inv0 = 1.0f / l0, inv1 = 1.0f / l1;
    u64 i0p = pk2(inv0, inv0), i1p = pk2(inv1, inv1);
    ulonglong2* O = (ulonglong2*)g_ao;
#pragma unroll
    for (int d = 0; d < 8; d++) {
        MUL2(o0[2 * d], i0p); MUL2(o0[2 * d + 1], i0p);
        MUL2(o1[2 * d], i1p); MUL2(o1[2 * d + 1], i1p);
        O[(nbase + tid) * 32 + h * 8 + d]       = make_ulonglong2(o0[2 * d], o0[2 * d + 1]);
        O[(nbase + tid + 256) * 32 + h * 8 + d] = make_ulonglong2(o1[2 * d], o1[2 * d + 1]);
    }
}

// ---------------- launch ----------------
extern "C" void kernel_launch(void* const* d_in, const int* in_sizes, int n_in,
                              void* d_out, int out_size) {
    const float* x    = (const float*)d_in[0];
    const int*   ei   = (const int*)d_in[1];
    const float* ee   = (const float*)d_in[2];
    const float* Wg   = (const float*)d_in[4];
    const float* bg   = (const float*)d_in[5];
    const float* root = (const float*)d_in[6];
    const float* Wq   = (const float*)d_in[7];
    const float* Wkv  = (const float*)d_in[8];
    const float* Wo   = (const float*)d_in[9];
    const float* bo   = (const float*)d_in[10];
    float* outp = (float*)d_out;

    float *p_h2, *p_ao, *p_wt;
    cudaGetSymbolAddress((void**)&p_h2, g_h2);
    cudaGetSymbolAddress((void**)&p_ao, g_ao);
    cudaGetSymbolAddress((void**)&p_wt, g_wt);

    const int GEMM_SMEM = (128 * 128 + 64 * 130) * 4;
    const int ATTN_SMEM = 128 * 1024;
    cudaFuncSetAttribute(scatter_gcn_kernel, cudaFuncAttributeMaxDynamicSharedMemorySize, GEMM_SMEM);
    cudaFuncSetAttribute(gemm_kernel,        cudaFuncAttributeMaxDynamicSharedMemorySize, GEMM_SMEM);
    cudaFuncSetAttribute(qkv_gemm_kernel,    cudaFuncAttributeMaxDynamicSharedMemorySize, GEMM_SMEM);
    cudaFuncSetAttribute(attn_kernel,        cudaFuncAttributeMaxDynamicSharedMemorySize, ATTN_SMEM);

    // 0: init + all weight transposes (fused)
    init_wtrans_kernel<<<256, dim3(32, 8)>>>(Wg, Wq, Wkv, Wo);
    // 1: fused scatter + GCN GEMM (overlapped atomic + FMA work)
    scatter_gcn_kernel<<<2560, 256, GEMM_SMEM>>>(ei, x, bg);
    // 2: gather -> h2
    gather_kernel<<<TN / 8, 256>>>(ee, root);
    // 3: fused q + kv projections  (PROFILED SLOT)
    qkv_gemm_kernel<<<dim3(TN / 128, 6), 256, GEMM_SMEM>>>(p_h2);
    // 4: attention
    attn_kernel<<<BG * NH, 256, ATTN_SMEM>>>();
    // 5: out = ao @ Wout + b_out
    gemm_kernel<<<dim3(TN / 128, 2), 256, GEMM_SMEM>>>(p_ao, p_wt + 65536, 128, bo, outp);
}

// round 8
// speedup vs baseline: 1.0689x; 1.0417x over previous
#include <cuda_runtime.h>
#include <cuda_bf16.h>
#include <cstdint>

#define TN   32768
#define D    128
#define BG   64
#define NG   512
#define ET   524288
#define NH   4
#define CAP  96

typedef unsigned long long u64;

// ---------------- scratch ----------------
__device__ float g_h  [TN * D];
__device__ float g_h2 [TN * D];
__device__ float g_q  [TN * D];
__device__ float g_kv [TN * 256];
__device__ float g_ao [TN * D];
__device__ float g_wt [640 * 128];   // wt0@0 (gcn), wt1@16384 (q), wt2@32768 (kv), wt3@65536 (out)
__device__ float g_deg[TN];
__device__ int   g_cnt[TN];
__device__ u64   g_bkt[TN * CAP];

// ---------------- f32x2 helpers ----------------
#define FMA2(d,a,b) asm("fma.rn.f32x2 %0, %1, %2, %0;" : "+l"(d) : "l"(a), "l"(b))
#define MUL2(d,a)   asm("mul.rn.f32x2 %0, %0, %1;"     : "+l"(d) : "l"(a))

__device__ __forceinline__ u64 pk2(float lo, float hi) {
    u64 r;
    asm("mov.b64 %0, {%1, %2};" : "=l"(r)
        : "r"(__float_as_uint(lo)), "r"(__float_as_uint(hi)));
    return r;
}
__device__ __forceinline__ float hadd2(u64 v) {
    unsigned int lo, hi;
    asm("mov.b64 {%0, %1}, %2;" : "=r"(lo), "=r"(hi) : "l"(v));
    return __uint_as_float(lo) + __uint_as_float(hi);
}

// ---------------- K0: fused init + weight transposes ----------------
__global__ void init_wtrans_kernel(const float* __restrict__ Wg,
                                   const float* __restrict__ Wq,
                                   const float* __restrict__ Wkv,
                                   const float* __restrict__ Wo) {
    __shared__ float t[32][33];
    int bid = blockIdx.x;
    if (bid < 128) {
        int i = bid * 256 + threadIdx.y * 32 + threadIdx.x;
        g_deg[i] = 1.0f;
        g_cnt[i] = 0;
        return;
    }
    int w = bid - 128;            // 0..127
    int z  = w >> 5;
    int by = (w >> 3) & 3;
    int bx = w & 7;
    const float* W; float* WT; int ncols;
    if (z == 0)      { W = Wg;  WT = g_wt;          ncols = 128; }
    else if (z == 1) { W = Wq;  WT = g_wt + 16384;  ncols = 128; }
    else if (z == 2) { W = Wkv; WT = g_wt + 32768;  ncols = 256; }
    else             { W = Wo;  WT = g_wt + 65536;  ncols = 128; }
    if (bx * 32 >= ncols) return;
    int c = bx * 32 + threadIdx.x;
    int k = by * 32 + threadIdx.y;
#pragma unroll
    for (int i = 0; i < 32; i += 8)
        t[threadIdx.y + i][threadIdx.x] = W[(k + i) * ncols + c];
    __syncthreads();
    int c2 = bx * 32 + threadIdx.y;
    int k2 = by * 32 + threadIdx.x;
#pragma unroll
    for (int i = 0; i < 32; i += 8)
        WT[(c2 + i) * 128 + k2] = t[threadIdx.x][threadIdx.y + i];
}

// ---------------- GEMM body (f32x2, 128x64 tile, conflict-free smem geometry) ----------------
// As: 128 rows x 132-float stride (16B aligned; warp rg-pairs land on disjoint banks)
// Ws: 64 cols  x 130-float stride ([c][k] u64 pairs; cols read at spacing 16 -> distinct banks)
// thread tile: rows rg+16*ri (ri<8), cols cg+16*j (j<4)
#define AS_STRIDE 132
#define GEMM_SMEM_FLOATS (128 * AS_STRIDE + 64 * 130)

__device__ __forceinline__ void gemm_body(const float* __restrict__ A,
                                          long long m0,
                                          const float* __restrict__ WTpart,
                                          const float* __restrict__ biasPart,
                                          float* __restrict__ out,
                                          int out_ld, int out_col0,
                                          float* sm) {
    float* As  = sm;
    float* WsT = sm + 128 * AS_STRIDE;
    int tid = threadIdx.x;

    const float4* A4 = (const float4*)(A + m0 * 128);
#pragma unroll
    for (int i = 0; i < 16; i++) {
        int idx = tid + i * 256;
        int r  = idx >> 5;
        int c4 = idx & 31;
        *(float4*)(As + r * AS_STRIDE + c4 * 4) = A4[idx];
    }

    const float4* WT4 = (const float4*)WTpart;
#pragma unroll
    for (int i = 0; i < 8; i++) {
        int idx = tid + i * 256;
        int c  = idx >> 5;
        int k4 = idx & 31;
        float4 w = WT4[idx];
        u64* dst = (u64*)(WsT + c * 130 + k4 * 4);
        dst[0] = ((const u64*)&w)[0];
        dst[1] = ((const u64*)&w)[1];
    }
    __syncthreads();

    int cg = tid & 15;
    int rg = tid >> 4;

    u64 acc[8][4];
#pragma unroll
    for (int i = 0; i < 8; i++)
#pragma unroll
        for (int j = 0; j < 4; j++) acc[i][j] = 0ull;

    const u64* Wu = (const u64*)WsT;   // per-col stride 65 u64

#pragma unroll 2
    for (int kk2 = 0; kk2 < 32; kk2++) {
        u64 w0[4], w1[4];
#pragma unroll
        for (int j = 0; j < 4; j++) {
            const u64* wp = Wu + (cg + 16 * j) * 65 + 2 * kk2;
            w0[j] = wp[0];
            w1[j] = wp[1];
        }
#pragma unroll
        for (int ri = 0; ri < 8; ri++) {
            ulonglong2 a2 = *(const ulonglong2*)(As + (rg + 16 * ri) * AS_STRIDE + kk2 * 4);
#pragma unroll
            for (int j = 0; j < 4; j++) {
                FMA2(acc[ri][j], a2.x, w0[j]);
                FMA2(acc[ri][j], a2.y, w1[j]);
            }
        }
    }

    float bb[4] = {0.f, 0.f, 0.f, 0.f};
    if (biasPart) {
#pragma unroll
        for (int j = 0; j < 4; j++) bb[j] = biasPart[cg + 16 * j];
    }
#pragma unroll
    for (int ri = 0; ri < 8; ri++) {
        long long row = m0 + rg + 16 * ri;
#pragma unroll
        for (int j = 0; j < 4; j++)
            out[row * out_ld + out_col0 + cg + 16 * j] = hadd2(acc[ri][j]) + bb[j];
    }
}

// ---------------- K1: fused scatter + GCN GEMM (interleaved 1:4) ----------------
__global__ void __launch_bounds__(256, 2)
scatter_gcn_kernel(const int* __restrict__ ei, const float* __restrict__ x,
                   const float* __restrict__ bg) {
    extern __shared__ float sm[];
    int bid = blockIdx.x;
    if (bid % 5 == 0) {
        int gid = bid / 5;               // 0..511
        int bx = gid & 255, by = gid >> 8;
        int cb = by * 64;
        gemm_body(x, (long long)bx * 128, g_wt + cb * 128, bg + cb,
                  g_h, 128, cb, sm);
    } else {
        int sid = bid - (bid / 5 + 1);   // 0..2047
        int e = sid * 256 + threadIdx.x;
        int r = ei[e];
        int c = ei[ET + e];
        atomicAdd(&g_deg[r], 1.0f);
        int pos = atomicAdd(&g_cnt[c], 1);
        if (pos < CAP)
            g_bkt[(long long)c * CAP + pos] = (u64)(unsigned)e | ((u64)(unsigned)r << 32);
    }
}

// standard GEMM: (TN x 128) @ (128 x ncols)
__global__ void __launch_bounds__(256, 2)
gemm_kernel(const float* __restrict__ A, const float* __restrict__ WT,
            int ncols, const float* __restrict__ bias, float* __restrict__ out) {
    extern __shared__ float sm[];
    int cb = blockIdx.y * 64;
    gemm_body(A, (long long)blockIdx.x * 128, WT + cb * 128,
              bias ? bias + cb : nullptr, out, ncols, cb, sm);
}

// fused q + kv projections: grid.y in [0,6)
__global__ void __launch_bounds__(256, 2)
qkv_gemm_kernel(const float* __restrict__ A) {
    extern __shared__ float sm[];
    int y = blockIdx.y;
    if (y < 2) {
        int cb = y * 64;
        gemm_body(A, (long long)blockIdx.x * 128, g_wt + 16384 + cb * 128,
                  nullptr, g_q, 128, cb, sm);
    } else {
        int cb = (y - 2) * 64;
        gemm_body(A, (long long)blockIdx.x * 128, g_wt + 32768 + cb * 128,
                  nullptr, g_kv, 256, cb, sm);
    }
}

// ---------------- K2: gather (warp-batched, MLP-unrolled) ----------------
__global__ void gather_kernel(const float* __restrict__ ee,
                              const float* __restrict__ root) {
    int gw = (blockIdx.x * blockDim.x + threadIdx.x) >> 5;
    int lane = threadIdx.x & 31;
    if (gw >= TN) return;
    int n = gw;
    float degn = g_deg[n];
    float dc = rsqrtf(degn);
    int cnt = g_cnt[n]; if (cnt > CAP) cnt = CAP;
    const float4* h4 = (const float4*)g_h;
    const float4* e4 = (const float4*)ee;
    const u64* bkt = g_bkt + (long long)n * CAP;
    float4 acc = make_float4(0.f, 0.f, 0.f, 0.f);

    for (int base = 0; base < cnt; base += 32) {
        int m = min(32, cnt - base);
        u64 pr = 0;
        if (lane < m) pr = bkt[base + lane];
        int r_l = (int)(unsigned)(pr >> 32);
        int e_l = (int)(unsigned)pr;
        float nm_l = 0.f;
        if (lane < m) nm_l = dc * rsqrtf(g_deg[r_l]);

        int p = 0;
        for (; p + 4 <= m; p += 4) {
            float4 hv[4], ev[4];
            float nm[4];
#pragma unroll
            for (int j = 0; j < 4; j++) {
                int r   = __shfl_sync(0xffffffffu, r_l, p + j);
                int eid = __shfl_sync(0xffffffffu, e_l, p + j);
                nm[j]   = __shfl_sync(0xffffffffu, nm_l, p + j);
                hv[j] = h4[r * 32 + lane];
                ev[j] = __ldcs(e4 + (long long)eid * 32 + lane);
            }
#pragma unroll
            for (int j = 0; j < 4; j++) {
                acc.x += nm[j] * fmaxf(hv[j].x + ev[j].x, 0.f);
                acc.y += nm[j] * fmaxf(hv[j].y + ev[j].y, 0.f);
                acc.z += nm[j] * fmaxf(hv[j].z + ev[j].z, 0.f);
                acc.w += nm[j] * fmaxf(hv[j].w + ev[j].w, 0.f);
            }
        }
        for (; p < m; p++) {
            int r   = __shfl_sync(0xffffffffu, r_l, p);
            int eid = __shfl_sync(0xffffffffu, e_l, p);
            float nm = __shfl_sync(0xffffffffu, nm_l, p);
            float4 hv = h4[r * 32 + lane];
            float4 ev = __ldcs(e4 + (long long)eid * 32 + lane);
            acc.x += nm * fmaxf(hv.x + ev.x, 0.f);
            acc.y += nm * fmaxf(hv.y + ev.y, 0.f);
            acc.z += nm * fmaxf(hv.z + ev.z, 0.f);
            acc.w += nm * fmaxf(hv.w + ev.w, 0.f);
        }
    }

    float4 hs = h4[n * 32 + lane];
    float4 rt = ((const float4*)root)[lane];
    float inv = 1.0f / degn;
    acc.x += fmaxf(hs.x + rt.x, 0.f) * inv;
    acc.y += fmaxf(hs.y + rt.y, 0.f) * inv;
    acc.z += fmaxf(hs.z + rt.z, 0.f) * inv;
    acc.w += fmaxf(hs.w + rt.w, 0.f) * inv;
    ((float4*)g_h2)[n * 32 + lane] = acc;
}

// ---------------- attention (frozen R2/R4 version) ----------------
__global__ void __launch_bounds__(256) attn_kernel() {
    extern __shared__ float sm[];
    float4* Ks4 = (float4*)sm;          // 512*8 float4 = 64KB
    float4* Vs4 = Ks4 + 512 * 8;        // 64KB
    int tid = threadIdx.x;
    int b = blockIdx.x >> 2;
    int h = blockIdx.x & 3;
    int nbase = b * NG;

    const float4* KV4 = (const float4*)g_kv;
    for (int idx = tid; idx < NG * 8; idx += 256) {
        int j  = idx >> 3;
        int d4 = idx & 7;
        Ks4[idx] = KV4[(nbase + j) * 64 + h * 8 + d4];
        Vs4[idx] = KV4[(nbase + j) * 64 + 32 + h * 8 + d4];
    }
    __syncthreads();

    const float scale = 0.17677669529663687f;
    u64 q0[16], q1[16];
    const float4* Q4 = (const float4*)g_q;
#pragma unroll
    for (int d4 = 0; d4 < 8; d4++) {
        float4 a = Q4[(nbase + tid) * 32 + h * 8 + d4];
        q0[2 * d4]     = pk2(a.x * scale, a.y * scale);
        q0[2 * d4 + 1] = pk2(a.z * scale, a.w * scale);
        float4 c = Q4[(nbase + tid + 256) * 32 + h * 8 + d4];
        q1[2 * d4]     = pk2(c.x * scale, c.y * scale);
        q1[2 * d4 + 1] = pk2(c.z * scale, c.w * scale);
    }

    u64 o0[16], o1[16];
#pragma unroll
    for (int d = 0; d < 16; d++) { o0[d] = 0ull; o1[d] = 0ull; }
    float m0 = -1e30f, l0 = 0.f, m1 = -1e30f, l1 = 0.f;

    for (int jt = 0; jt < NG; jt += 8) {
        float s0[8], s1[8];
#pragma unroll
        for (int jj = 0; jj < 8; jj++) {
            const ulonglong2* kp = (const ulonglong2*)(Ks4 + (jt + jj) * 8);
            u64 a0 = 0ull, b0 = 0ull, a1 = 0ull, b1 = 0ull;
#pragma unroll
            for (int d = 0; d < 8; d++) {
                ulonglong2 kk = kp[d];
                FMA2(a0, q0[2 * d], kk.x);
                FMA2(b0, q0[2 * d + 1], kk.y);
                FMA2(a1, q1[2 * d], kk.x);
                FMA2(b1, q1[2 * d + 1], kk.y);
            }
            s0[jj] = hadd2(a0) + hadd2(b0);
            s1[jj] = hadd2(a1) + hadd2(b1);
        }
        float tm0 = s0[0], tm1 = s1[0];
#pragma unroll
        for (int jj = 1; jj < 8; jj++) { tm0 = fmaxf(tm0, s0[jj]); tm1 = fmaxf(tm1, s1[jj]); }
        float nm0 = fmaxf(m0, tm0), nm1 = fmaxf(m1, tm1);
        float al0 = __expf(m0 - nm0), al1 = __expf(m1 - nm1);
        m0 = nm0; m1 = nm1;
        l0 *= al0; l1 *= al1;
        u64 al0p = pk2(al0, al0), al1p = pk2(al1, al1);
#pragma unroll
        for (int d = 0; d < 16; d++) { MUL2(o0[d], al0p); MUL2(o1[d], al1p); }
#pragma unroll
        for (int jj = 0; jj < 8; jj++) {
            float p0 = __expf(s0[jj] - m0); l0 += p0;
            float p1 = __expf(s1[jj] - m1); l1 += p1;
            u64 p0p = pk2(p0, p0), p1p = pk2(p1, p1);
            const ulonglong2* vp = (const ulonglong2*)(Vs4 + (jt + jj) * 8);
#pragma unroll
            for (int d = 0; d < 8; d++) {
                ulonglong2 vv = vp[d];
                FMA2(o0[2 * d],     p0p, vv.x);
                FMA2(o0[2 * d + 1], p0p, vv.y);
                FMA2(o1[2 * d],     p1p, vv.x);
                FMA2(o1[2 * d + 1], p1p, vv.y);
            }
        }
    }

    float inv0 = 1.0f / l0, inv1 = 1.0f / l1;
    u64 i0p = pk2(inv0, inv0), i1p = pk2(inv1, inv1);
    ulonglong2* O = (ulonglong2*)g_ao;
#pragma unroll
    for (int d = 0; d < 8; d++) {
        MUL2(o0[2 * d], i0p); MUL2(o0[2 * d + 1], i0p);
        MUL2(o1[2 * d], i1p); MUL2(o1[2 * d + 1], i1p);
        O[(nbase + tid) * 32 + h * 8 + d]       = make_ulonglong2(o0[2 * d], o0[2 * d + 1]);
        O[(nbase + tid + 256) * 32 + h * 8 + d] = make_ulonglong2(o1[2 * d], o1[2 * d + 1]);
    }
}

// ---------------- launch ----------------
extern "C" void kernel_launch(void* const* d_in, const int* in_sizes, int n_in,
                              void* d_out, int out_size) {
    const float* x    = (const float*)d_in[0];
    const int*   ei   = (const int*)d_in[1];
    const float* ee   = (const float*)d_in[2];
    const float* Wg   = (const float*)d_in[4];
    const float* bg   = (const float*)d_in[5];
    const float* root = (const float*)d_in[6];
    const float* Wq   = (const float*)d_in[7];
    const float* Wkv  = (const float*)d_in[8];
    const float* Wo   = (const float*)d_in[9];
    const float* bo   = (const float*)d_in[10];
    float* outp = (float*)d_out;

    float *p_h2, *p_ao, *p_wt;
    cudaGetSymbolAddress((void**)&p_h2, g_h2);
    cudaGetSymbolAddress((void**)&p_ao, g_ao);
    cudaGetSymbolAddress((void**)&p_wt, g_wt);

    const int GEMM_SMEM = GEMM_SMEM_FLOATS * 4;   // 100864 B
    const int ATTN_SMEM = 128 * 1024;
    cudaFuncSetAttribute(scatter_gcn_kernel, cudaFuncAttributeMaxDynamicSharedMemorySize, GEMM_SMEM);
    cudaFuncSetAttribute(gemm_kernel,        cudaFuncAttributeMaxDynamicSharedMemorySize, GEMM_SMEM);
    cudaFuncSetAttribute(qkv_gemm_kernel,    cudaFuncAttributeMaxDynamicSharedMemorySize, GEMM_SMEM);
    cudaFuncSetAttribute(attn_kernel,        cudaFuncAttributeMaxDynamicSharedMemorySize, ATTN_SMEM);

    // 0: init + all weight transposes (fused)
    init_wtrans_kernel<<<256, dim3(32, 8)>>>(Wg, Wq, Wkv, Wo);
    // 1: fused scatter + GCN GEMM
    scatter_gcn_kernel<<<2560, 256, GEMM_SMEM>>>(ei, x, bg);
    // 2: gather -> h2
    gather_kernel<<<TN / 8, 256>>>(ee, root);
    // 3: fused q + kv projections  (PROFILED SLOT)
    qkv_gemm_kernel<<<dim3(TN / 128, 6), 256, GEMM_SMEM>>>(p_h2);
    // 4: attention
    attn_kernel<<<BG * NH, 256, ATTN_SMEM>>>();
    // 5: out = ao @ Wout + b_out
    gemm_kernel<<<dim3(TN / 128, 2), 256, GEMM_SMEM>>>(p_ao, p_wt + 65536, 128, bo, outp);
}